// round 7
// baseline (speedup 1.0000x reference)
#include <cuda_runtime.h>
#include <cuda_bf16.h>
#include <cstdint>

#define B_  512
#define T_  64
#define H_  512
#define G_  1536
#define KP0 320

#define BND   0.04419417382415922f           /* 1/sqrt(512) */
#define WQS   (16256.0f / 0.04419417382415922f)
#define CSC_  (0.04419417382415922f / (16256.0f * 16256.0f))

// ---------------- scratch ----------------------------------------------------
__device__ float g_gx0 [(size_t)B_ * T_ * 2 * G_];
__device__ float g_gx1 [(size_t)B_ * T_ * G_];
__device__ float g_gx1b[(size_t)B_ * G_];
__device__ float g_h   [2 * 2 * B_ * H_];
__device__ float g_lastb[(size_t)B_ * H_];
__device__ unsigned g_bar[2048];
__device__ __align__(16) __nv_bfloat16 g_a0hi[(size_t)B_ * T_ * KP0];
__device__ __align__(16) __nv_bfloat16 g_a0lo[(size_t)B_ * T_ * KP0];
__device__ __align__(16) __nv_bfloat16 g_w0hi[(size_t)2 * G_ * KP0];
__device__ __align__(16) __nv_bfloat16 g_w0lo[(size_t)2 * G_ * KP0];
// int8 planes
__device__ __align__(16) int8_t g_hq1 [2 * 2 * B_ * H_];
__device__ __align__(16) int8_t g_hq0 [2 * 2 * B_ * H_];
__device__ __align__(16) int8_t g_yq1 [(size_t)B_ * T_ * 2 * H_];
__device__ __align__(16) int8_t g_yq0 [(size_t)B_ * T_ * 2 * H_];
__device__ __align__(16) int8_t g_w1q1[(size_t)2 * G_ * 2 * H_];
__device__ __align__(16) int8_t g_w1q0[(size_t)2 * G_ * 2 * H_];
__device__ __align__(16) int8_t g_wh0q1[(size_t)2 * G_ * H_];
__device__ __align__(16) int8_t g_wh0q0[(size_t)2 * G_ * H_];
__device__ __align__(16) int8_t g_wh1q1[(size_t)2 * G_ * H_];
__device__ __align__(16) int8_t g_wh1q0[(size_t)2 * G_ * H_];

// ---------------- helpers ----------------------------------------------------
__device__ __forceinline__ uint32_t smem_u32(const void* p) {
    uint32_t a;
    asm("{ .reg .u64 t; cvta.to.shared.u64 t, %1; cvt.u32.u64 %0, t; }" : "=r"(a) : "l"(p));
    return a;
}
#define CP16(sm, gp)  asm volatile("cp.async.cg.shared.global [%0], [%1], 16;" :: "r"(sm), "l"(gp))
#define CP_COMMIT()   asm volatile("cp.async.commit_group;" ::: "memory")
#define CP_WAIT(n)    asm volatile("cp.async.wait_group %0;" :: "n"(n) : "memory")

__device__ __forceinline__ void ldsm4(uint32_t* r, uint32_t a) {
    asm volatile("ldmatrix.sync.aligned.m8n8.x4.shared.b16 {%0,%1,%2,%3}, [%4];"
        : "=r"(r[0]), "=r"(r[1]), "=r"(r[2]), "=r"(r[3]) : "r"(a));
}
__device__ __forceinline__ void ldsm2(uint32_t* r, uint32_t a) {
    asm volatile("ldmatrix.sync.aligned.m8n8.x2.shared.b16 {%0,%1}, [%2];"
        : "=r"(r[0]), "=r"(r[1]) : "r"(a));
}
__device__ __forceinline__ void mma16816(float* c, const uint32_t* a, const uint32_t* b) {
    asm volatile("mma.sync.aligned.m16n8k16.row.col.f32.bf16.bf16.f32 "
        "{%0,%1,%2,%3},{%4,%5,%6,%7},{%8,%9},{%0,%1,%2,%3};"
        : "+f"(c[0]), "+f"(c[1]), "+f"(c[2]), "+f"(c[3])
        : "r"(a[0]), "r"(a[1]), "r"(a[2]), "r"(a[3]), "r"(b[0]), "r"(b[1]));
}
__device__ __forceinline__ void mma_s8(int* c, const uint32_t* a, const uint32_t* b) {
    asm volatile("mma.sync.aligned.m16n8k32.row.col.s32.s8.s8.s32 "
        "{%0,%1,%2,%3},{%4,%5,%6,%7},{%8,%9},{%0,%1,%2,%3};"
        : "+r"(c[0]), "+r"(c[1]), "+r"(c[2]), "+r"(c[3])
        : "r"(a[0]), "r"(a[1]), "r"(a[2]), "r"(a[3]), "r"(b[0]), "r"(b[1]));
}
__device__ __forceinline__ float sigm(float x) { return __fdividef(1.f, 1.f + __expf(-x)); }
__device__ __forceinline__ float tanh_(float x) { return 2.f * sigm(2.f * x) - 1.f; }
__device__ __forceinline__ void quant15(float v, int8_t* hi, int8_t* lo) {
    int q = __float2int_rn(v * 16256.f);
    int h = (q + 64) >> 7;
    *hi = (int8_t)h; *lo = (int8_t)(q - (h << 7));
}

__device__ __forceinline__ void grid_bar(unsigned* c, unsigned target) {
    __syncthreads();
    if (threadIdx.x == 0) {
        __threadfence();
        atomicAdd(c, 1u);
        while (atomicAdd(c, 0u) < target) { }
        __threadfence();
    }
    __syncthreads();
}

// ---------------- prep kernels ----------------------------------------------
__global__ void embed_split_kernel(const int* __restrict__ tokens,
                                   const float* __restrict__ emb,
                                   __nv_bfloat16* __restrict__ hi,
                                   __nv_bfloat16* __restrict__ lo)
{
    const int blk = blockIdx.x;
    const int t = blk / B_;
    const int b = blk - t * B_;
    const int tok = tokens[b * T_ + t];
    const float* src = emb + (size_t)tok * 300;
    size_t dst = (size_t)blk * KP0;
    for (int e = threadIdx.x; e < KP0; e += blockDim.x) {
        float v = (e < 300) ? src[e] : 0.f;
        __nv_bfloat16 h = __float2bfloat16(v);
        hi[dst + e] = h;
        lo[dst + e] = __float2bfloat16(v - __bfloat162float(h));
    }
}

__global__ void split_pad_kernel(const float* __restrict__ src,
                                 __nv_bfloat16* __restrict__ hi,
                                 __nv_bfloat16* __restrict__ lo,
                                 int rows, int K, int Kp)
{
    size_t idx = (size_t)blockIdx.x * blockDim.x + threadIdx.x;
    if (idx >= (size_t)rows * Kp) return;
    int r = (int)(idx / Kp);
    int c = (int)(idx - (size_t)r * Kp);
    float v = (c < K) ? src[(size_t)r * K + c] : 0.f;
    __nv_bfloat16 h = __float2bfloat16(v);
    hi[idx] = h;
    lo[idx] = __float2bfloat16(v - __bfloat162float(h));
}

__global__ void split_i8_kernel(const float* __restrict__ src,
                                int8_t* __restrict__ q1, int8_t* __restrict__ q0,
                                int n)
{
    int idx = blockIdx.x * blockDim.x + threadIdx.x;
    if (idx >= n) return;
    int q = __float2int_rn(src[idx] * WQS);
    int h = (q + 64) >> 7;
    q1[idx] = (int8_t)h;
    q0[idx] = (int8_t)(q - (h << 7));
}

__global__ void zero_ctr_kernel(unsigned* __restrict__ p, int n)
{
    int i = blockIdx.x * blockDim.x + threadIdx.x;
    if (i < n) p[i] = 0u;
}

// ---------------- bf16-split GEMM (layer0 input only; proven) --------------
#define SSTR 80
#define TILE_B (128 * SSTR)
#define STAGE_B (4 * TILE_B)
__global__ void __launch_bounds__(256, 1)
gemm_mma_split(const __nv_bfloat16* __restrict__ Ahi,
               const __nv_bfloat16* __restrict__ Alo,
               const __nv_bfloat16* __restrict__ Whi,
               const __nv_bfloat16* __restrict__ Wlo,
               const float* __restrict__ bias,
               float* __restrict__ C, int N, int Kp)
{
    extern __shared__ __align__(16) char smem[];
    const int tid = threadIdx.x;
    const int lane = tid & 31;
    const int wid = tid >> 5;
    const int wm = wid & 1, wn = wid >> 1;
    const int m0c = blockIdx.y * 128, n0c = blockIdx.x * 128;
    const int nchunks = Kp >> 5;
    const uint32_t sbase = smem_u32(smem);
    const __nv_bfloat16* bases[4] = { Ahi, Alo, Whi, Wlo };

    auto load_chunk = [&](int c, int s) {
        const uint32_t st = sbase + s * STAGE_B;
        #pragma unroll
        for (int q = 0; q < 8; q++) {
            int g = tid + q * 256;
            int tile = g >> 9, p = g & 511;
            int r = p >> 2, seg = p & 3;
            int rowbase = (tile < 2) ? m0c : n0c;
            CP16(st + tile * TILE_B + r * SSTR + seg * 16,
                 bases[tile] + (size_t)(rowbase + r) * Kp + c * 32 + seg * 8);
        }
        CP_COMMIT();
    };

    float acc[16][4];
    #pragma unroll
    for (int i = 0; i < 16; i++)
        #pragma unroll
        for (int j = 0; j < 4; j++) acc[i][j] = 0.f;

    load_chunk(0, 0);
    for (int c = 0; c < nchunks; c++) {
        const int s = c & 1;
        if (c + 1 < nchunks) { load_chunk(c + 1, s ^ 1); CP_WAIT(1); }
        else                 { CP_WAIT(0); }
        __syncthreads();
        const uint32_t st = sbase + s * STAGE_B;
        #pragma unroll
        for (int kk = 0; kk < 2; kk++) {
            uint32_t ahi[4][4], alo[4][4], bhi[4][2], blo[4][2];
            #pragma unroll
            for (int i = 0; i < 4; i++) {
                int row = wm * 64 + i * 16 + (lane & 15);
                uint32_t off = row * SSTR + kk * 32 + (lane >> 4) * 16;
                ldsm4(ahi[i], st + off);
                ldsm4(alo[i], st + TILE_B + off);
            }
            #pragma unroll
            for (int j = 0; j < 4; j++) {
                int row = wn * 32 + j * 8 + (lane & 7);
                uint32_t off = row * SSTR + kk * 32 + ((lane >> 3) & 1) * 16;
                ldsm2(bhi[j], st + 2 * TILE_B + off);
                ldsm2(blo[j], st + 3 * TILE_B + off);
            }
            #pragma unroll
            for (int i = 0; i < 4; i++)
                #pragma unroll
                for (int j = 0; j < 4; j++) {
                    mma16816(acc[i * 4 + j], ahi[i], bhi[j]);
                    mma16816(acc[i * 4 + j], ahi[i], blo[j]);
                    mma16816(acc[i * 4 + j], alo[i], bhi[j]);
                }
        }
        __syncthreads();
    }
    #pragma unroll
    for (int i = 0; i < 4; i++) {
        int m = m0c + wm * 64 + i * 16 + (lane >> 2);
        #pragma unroll
        for (int j = 0; j < 4; j++) {
            int n = n0c + wn * 32 + j * 8 + (lane & 3) * 2;
            float b0 = bias[n], b1 = bias[n + 1];
            float* a = acc[i * 4 + j];
            float2 v0 = { a[0] + b0, a[1] + b1 };
            float2 v1 = { a[2] + b0, a[3] + b1 };
            *reinterpret_cast<float2*>(C + (size_t)m * N + n) = v0;
            *reinterpret_cast<float2*>(C + (size_t)(m + 8) * N + n) = v1;
        }
    }
}

// ---------------- int8 split GEMM (layer1 input GEMMs) ---------------------
// C = outscale*(acc14*16384 + acc7*128) + bias; K-chunk 64 int8, 2 stages.
__global__ void __launch_bounds__(256, 1)
gemm_i8_split(const int8_t* __restrict__ Aq1, const int8_t* __restrict__ Aq0,
              const int8_t* __restrict__ Wq1, const int8_t* __restrict__ Wq0,
              const float* __restrict__ bias, float outscale,
              float* __restrict__ C, int N, int Kp)
{
    extern __shared__ __align__(16) char smem[];
    const int TB = 128 * SSTR;
    const int STGB = 4 * TB;
    const int tid = threadIdx.x;
    const int lane = tid & 31;
    const int wid = tid >> 5;
    const int wm = wid & 1, wn = wid >> 1;
    const int m0c = blockIdx.y * 128, n0c = blockIdx.x * 128;
    const int nchunks = Kp >> 6;
    const uint32_t sbase = smem_u32(smem);
    const int8_t* bases[4] = { Aq1, Aq0, Wq1, Wq0 };

    auto load_chunk = [&](int c, int s) {
        const uint32_t st = sbase + s * STGB;
        #pragma unroll
        for (int q = 0; q < 8; q++) {
            int g = tid + q * 256;
            int tile = g >> 9, p = g & 511;
            int r = p >> 2, seg = p & 3;
            int rowbase = (tile < 2) ? m0c : n0c;
            CP16(st + tile * TB + r * SSTR + seg * 16,
                 bases[tile] + (size_t)(rowbase + r) * Kp + c * 64 + seg * 16);
        }
        CP_COMMIT();
    };

    int acc14[16][4], acc7[16][4];
    #pragma unroll
    for (int i = 0; i < 16; i++)
        #pragma unroll
        for (int j = 0; j < 4; j++) { acc14[i][j] = 0; acc7[i][j] = 0; }

    load_chunk(0, 0);
    for (int c = 0; c < nchunks; c++) {
        const int s = c & 1;
        if (c + 1 < nchunks) { load_chunk(c + 1, s ^ 1); CP_WAIT(1); }
        else                 { CP_WAIT(0); }
        __syncthreads();
        const uint32_t st = sbase + s * STGB;
        #pragma unroll
        for (int kk = 0; kk < 2; kk++) {
            uint32_t a1[4][4], a0[4][4], b1[4][2], b0[4][2];
            #pragma unroll
            for (int i = 0; i < 4; i++) {
                int row = wm * 64 + i * 16 + (lane & 15);
                uint32_t off = row * SSTR + kk * 32 + (lane >> 4) * 16;
                ldsm4(a1[i], st + off);
                ldsm4(a0[i], st + TB + off);
            }
            #pragma unroll
            for (int j = 0; j < 4; j++) {
                int row = wn * 32 + j * 8 + (lane & 7);
                uint32_t off = row * SSTR + kk * 32 + ((lane >> 3) & 1) * 16;
                ldsm2(b1[j], st + 2 * TB + off);
                ldsm2(b0[j], st + 3 * TB + off);
            }
            #pragma unroll
            for (int i = 0; i < 4; i++)
                #pragma unroll
                for (int j = 0; j < 4; j++) {
                    mma_s8(acc14[i * 4 + j], a1[i], b1[j]);
                    mma_s8(acc7[i * 4 + j],  a1[i], b0[j]);
                    mma_s8(acc7[i * 4 + j],  a0[i], b1[j]);
                }
        }
        __syncthreads();
    }
    #pragma unroll
    for (int i = 0; i < 4; i++) {
        int m = m0c + wm * 64 + i * 16 + (lane >> 2);
        #pragma unroll
        for (int j = 0; j < 4; j++) {
            int n = n0c + wn * 32 + j * 8 + (lane & 3) * 2;
            float b0v = bias[n], b1v = bias[n + 1];
            int* a14 = acc14[i * 4 + j];
            int* a7  = acc7[i * 4 + j];
            float2 v0, v1;
            v0.x = outscale * ((float)a14[0] * 16384.f + (float)a7[0] * 128.f) + b0v;
            v0.y = outscale * ((float)a14[1] * 16384.f + (float)a7[1] * 128.f) + b1v;
            v1.x = outscale * ((float)a14[2] * 16384.f + (float)a7[2] * 128.f) + b0v;
            v1.y = outscale * ((float)a14[3] * 16384.f + (float)a7[3] * 128.f) + b1v;
            *reinterpret_cast<float2*>(C + (size_t)m * N + n) = v0;
            *reinterpret_cast<float2*>(C + (size_t)(m + 8) * N + n) = v1;
        }
    }
}

// ---------------- PERSISTENT int8 GRU scan ----------------------------------
template<int NJF>
__global__ void __launch_bounds__(256, 1)
gru_scan_i8(float* __restrict__ h_A, float* __restrict__ h_B,
            int8_t* __restrict__ hq1_A, int8_t* __restrict__ hq0_A,
            int8_t* __restrict__ hq1_B, int8_t* __restrict__ hq0_B,
            const float* __restrict__ gx, int gx_ld, int gx_ds,
            const int8_t* __restrict__ wq1, const int8_t* __restrict__ wq0,
            const float* __restrict__ bhh,
            int8_t* __restrict__ yq1, int8_t* __restrict__ yq0,
            unsigned* __restrict__ bars)
{
    constexpr int JT = 32 * NJF;
    constexpr int WROWS = 3 * JT;
    constexpr int A_B = 64 * SSTR;
    constexpr int W_B = WROWS * SSTR;
    constexpr int STG = 2 * A_B + 2 * W_B;
    constexpr int NPC = 512 + WROWS * 8;
    constexpr int SH = (NJF == 2) ? 6 : 5;

    extern __shared__ __align__(16) char smem[];
    const int tid = threadIdx.x;
    const int lane = tid & 31;
    const int wid = tid >> 5;
    const int wm = wid & 1, wn = wid >> 1;
    const int d  = blockIdx.z;
    const int b0 = blockIdx.x * 64;
    const int j0 = blockIdx.y * JT;
    const uint32_t sb = smem_u32(smem);
    // sub-barrier: CTAs sharing (b-block, dir)
    unsigned* ctr = bars + (blockIdx.x * gridDim.z + blockIdx.z) * 32;
    const unsigned members = gridDim.y;

    const int8_t* W1 = wq1 + (size_t)d * G_ * H_;
    const int8_t* W0 = wq0 + (size_t)d * G_ * H_;
    const float* bhh_d = bhh + d * G_;

    float* hp = h_A;  float* hn = h_B;
    const int8_t *pq1 = hq1_A, *pq0 = hq0_A;
    int8_t *nq1 = hq1_B, *nq0 = hq0_B;

    for (int s = 0; s < T_; s++) {
        const int t = (d == 0) ? s : (T_ - 1 - s);

        int acc14[3][2][NJF][4], acc7[3][2][NJF][4];
        #pragma unroll
        for (int g = 0; g < 3; g++)
            #pragma unroll
            for (int i = 0; i < 2; i++)
                #pragma unroll
                for (int jf = 0; jf < NJF; jf++)
                    #pragma unroll
                    for (int r = 0; r < 4; r++) { acc14[g][i][jf][r] = 0; acc7[g][i][jf][r] = 0; }

        if (s > 0) {
            const int8_t* A1 = pq1 + (size_t)d * B_ * H_;
            const int8_t* A0 = pq0 + (size_t)d * B_ * H_;

            auto load_chunk = [&](int c, int st) {
                const uint32_t base = sb + st * STG;
                #pragma unroll
                for (int q = 0; q < NPC / 256; q++) {
                    int g = tid + q * 256;
                    uint32_t soff;
                    const int8_t* gp;
                    if (g < 512) {
                        int hi = (g < 256);
                        int p = g & 255;
                        int r = p >> 2, seg = p & 3;
                        gp = (hi ? A1 : A0) + (size_t)(b0 + r) * H_ + c * 64 + seg * 16;
                        soff = base + (hi ? 0 : A_B) + r * SSTR + seg * 16;
                    } else {
                        int gw = g - 512;
                        int hi = (gw < WROWS * 4);
                        int p = hi ? gw : gw - WROWS * 4;
                        int r = p >> 2, seg = p & 3;
                        int grow = ((r >> SH) << 9) + j0 + (r & (JT - 1));
                        gp = (hi ? W1 : W0) + (size_t)grow * H_ + c * 64 + seg * 16;
                        soff = base + 2 * A_B + (hi ? 0 : W_B) + r * SSTR + seg * 16;
                    }
                    CP16(soff, gp);
                }
                CP_COMMIT();
            };

            load_chunk(0, 0);
            for (int c = 0; c < H_ / 64; c++) {
                const int st = c & 1;
                if (c + 1 < H_ / 64) { load_chunk(c + 1, st ^ 1); CP_WAIT(1); }
                else                 { CP_WAIT(0); }
                __syncthreads();
                const uint32_t base = sb + st * STG;
                #pragma unroll
                for (int kk = 0; kk < 2; kk++) {
                    uint32_t a1[2][4], a0[2][4];
                    #pragma unroll
                    for (int i = 0; i < 2; i++) {
                        int row = wm * 32 + i * 16 + (lane & 15);
                        uint32_t off = row * SSTR + kk * 32 + (lane >> 4) * 16;
                        ldsm4(a1[i], base + off);
                        ldsm4(a0[i], base + A_B + off);
                    }
                    uint32_t b1[3][NJF][2], b0[3][NJF][2];
                    #pragma unroll
                    for (int g = 0; g < 3; g++)
                        #pragma unroll
                        for (int jf = 0; jf < NJF; jf++) {
                            int row = g * JT + wn * 8 * NJF + jf * 8 + (lane & 7);
                            uint32_t off = row * SSTR + kk * 32 + ((lane >> 3) & 1) * 16;
                            ldsm2(b1[g][jf], base + 2 * A_B + off);
                            ldsm2(b0[g][jf], base + 2 * A_B + W_B + off);
                        }
                    #pragma unroll
                    for (int g = 0; g < 3; g++)
                        #pragma unroll
                        for (int i = 0; i < 2; i++)
                            #pragma unroll
                            for (int jf = 0; jf < NJF; jf++) {
                                mma_s8(acc14[g][i][jf], a1[i], b1[g][jf]);
                                mma_s8(acc7[g][i][jf],  a1[i], b0[g][jf]);
                                mma_s8(acc7[g][i][jf],  a0[i], b1[g][jf]);
                            }
                }
                __syncthreads();
            }
        }

        // -------- gate epilogue --------
        #pragma unroll
        for (int i = 0; i < 2; i++)
            #pragma unroll
            for (int jf = 0; jf < NJF; jf++)
                #pragma unroll
                for (int half = 0; half < 2; half++) {
                    int b = b0 + wm * 32 + i * 16 + (lane >> 2) + half * 8;
                    size_t row = (size_t)t * B_ + b;
                    const float* gxr = gx + row * gx_ld + (size_t)d * gx_ds;
                    const float* hpr = hp + ((size_t)d * B_ + b) * H_;
                    int jc = j0 + wn * 8 * NJF + jf * 8 + (lane & 3) * 2;
                    #pragma unroll
                    for (int e = 0; e < 2; e++) {
                        int j = jc + e;
                        int r2 = half * 2 + e;
                        float ghr = CSC_ * ((float)acc14[0][i][jf][r2] * 16384.f
                                          + (float)acc7[0][i][jf][r2] * 128.f) + bhh_d[j];
                        float ghz = CSC_ * ((float)acc14[1][i][jf][r2] * 16384.f
                                          + (float)acc7[1][i][jf][r2] * 128.f) + bhh_d[H_ + j];
                        float ghn = CSC_ * ((float)acc14[2][i][jf][r2] * 16384.f
                                          + (float)acc7[2][i][jf][r2] * 128.f) + bhh_d[2 * H_ + j];
                        float rg = sigm(gxr[j] + ghr);
                        float zg = sigm(gxr[H_ + j] + ghz);
                        float ng = tanh_(gxr[2 * H_ + j] + rg * ghn);
                        float hprev = (s > 0) ? hpr[j] : 0.f;
                        float hv = (1.f - zg) * ng + zg * hprev;
                        size_t ho = ((size_t)d * B_ + b) * H_ + j;
                        hn[ho] = hv;
                        int8_t qh, ql;
                        quant15(hv, &qh, &ql);
                        nq1[ho] = qh; nq0[ho] = ql;
                        if (yq1) {
                            size_t yo = row * (size_t)(2 * H_) + (size_t)d * H_ + j;
                            yq1[yo] = qh; yq0[yo] = ql;
                        }
                    }
                }

        grid_bar(ctr, (unsigned)(s + 1) * members);

        float* tf = hp; hp = hn; hn = tf;
        const int8_t* t1 = pq1; pq1 = nq1; nq1 = (int8_t*)t1;
        const int8_t* t0 = pq0; pq0 = nq0; nq0 = (int8_t*)t0;
    }
}

// ---------------- tail kernels ----------------------------------------------
__global__ void bwd1_gates(const float* __restrict__ gxb,
                           const float* __restrict__ bhh,
                           float* __restrict__ out)
{
    int idx = blockIdx.x * blockDim.x + threadIdx.x;
    if (idx >= B_ * H_) return;
    int b = idx >> 9, j = idx & 511;
    const float* r0 = gxb + (size_t)b * G_;
    float rg = sigm(r0[j] + bhh[j]);
    float zg = sigm(r0[H_ + j] + bhh[H_ + j]);
    float ng = tanh_(r0[2 * H_ + j] + rg * bhh[2 * H_ + j]);
    out[idx] = (1.f - zg) * ng;
}

__global__ void fc_kernel(const float* __restrict__ hf, const float* __restrict__ hb,
                          const float* __restrict__ fcw, const float* __restrict__ fcb,
                          float* __restrict__ out)
{
    int b = blockIdx.x, tid = threadIdx.x;
    float s0 = 0.f, s1 = 0.f;
    for (int j = tid; j < 1024; j += 256) {
        float v = (j < 512) ? hf[(size_t)b * 512 + j] : hb[(size_t)b * 512 + (j - 512)];
        s0 += v * fcw[j];
        s1 += v * fcw[1024 + j];
    }
    __shared__ float red0[256], red1[256];
    red0[tid] = s0; red1[tid] = s1;
    __syncthreads();
    for (int off = 128; off > 0; off >>= 1) {
        if (tid < off) { red0[tid] += red0[tid + off]; red1[tid] += red1[tid + off]; }
        __syncthreads();
    }
    if (tid == 0) {
        out[b * 2 + 0] = red0[0] + fcb[0];
        out[b * 2 + 1] = red1[0] + fcb[1];
    }
}

// ---------------- launch -----------------------------------------------------
extern "C" void kernel_launch(void* const* d_in, const int* in_sizes, int n_in,
                              void* d_out, int out_size)
{
    (void)in_sizes; (void)n_in; (void)out_size;
    const int*   tokens = (const int*)  d_in[0];
    const float* emb    = (const float*)d_in[1];
    const float* w_ih0  = (const float*)d_in[2];
    const float* w_hh0  = (const float*)d_in[3];
    const float* b_ih0  = (const float*)d_in[4];
    const float* b_hh0  = (const float*)d_in[5];
    const float* w_ih1  = (const float*)d_in[6];
    const float* w_hh1  = (const float*)d_in[7];
    const float* b_ih1  = (const float*)d_in[8];
    const float* b_hh1  = (const float*)d_in[9];
    const float* fc_w   = (const float*)d_in[10];
    const float* fc_b   = (const float*)d_in[11];
    float* out = (float*)d_out;

    float *pgx0, *pgx1, *pgx1b, *ph, *plastb;
    unsigned* pbar;
    cudaGetSymbolAddress((void**)&pgx0,   g_gx0);
    cudaGetSymbolAddress((void**)&pgx1,   g_gx1);
    cudaGetSymbolAddress((void**)&pgx1b,  g_gx1b);
    cudaGetSymbolAddress((void**)&ph,     g_h);
    cudaGetSymbolAddress((void**)&plastb, g_lastb);
    cudaGetSymbolAddress((void**)&pbar,   g_bar);
    __nv_bfloat16 *pa0hi, *pa0lo, *pw0hi, *pw0lo;
    cudaGetSymbolAddress((void**)&pa0hi, g_a0hi);
    cudaGetSymbolAddress((void**)&pa0lo, g_a0lo);
    cudaGetSymbolAddress((void**)&pw0hi, g_w0hi);
    cudaGetSymbolAddress((void**)&pw0lo, g_w0lo);
    int8_t *phq1, *phq0, *pyq1, *pyq0, *pw1q1, *pw1q0;
    int8_t *pwh0q1, *pwh0q0, *pwh1q1, *pwh1q0;
    cudaGetSymbolAddress((void**)&phq1, g_hq1);
    cudaGetSymbolAddress((void**)&phq0, g_hq0);
    cudaGetSymbolAddress((void**)&pyq1, g_yq1);
    cudaGetSymbolAddress((void**)&pyq0, g_yq0);
    cudaGetSymbolAddress((void**)&pw1q1, g_w1q1);
    cudaGetSymbolAddress((void**)&pw1q0, g_w1q0);
    cudaGetSymbolAddress((void**)&pwh0q1, g_wh0q1);
    cudaGetSymbolAddress((void**)&pwh0q0, g_wh0q0);
    cudaGetSymbolAddress((void**)&pwh1q1, g_wh1q1);
    cudaGetSymbolAddress((void**)&pwh1q0, g_wh1q0);

    const int GSM = 2 * STAGE_B;                              // 81920
    const int SSM2 = 2 * (2 * 64 * SSTR + 2 * 192 * SSTR);    // 81920 (NJF=2)
    const int SSM1 = 2 * (2 * 64 * SSTR + 2 * 96 * SSTR);     // 51200 (NJF=1)
    cudaFuncSetAttribute(gemm_mma_split, cudaFuncAttributeMaxDynamicSharedMemorySize, GSM);
    cudaFuncSetAttribute(gemm_i8_split,  cudaFuncAttributeMaxDynamicSharedMemorySize, GSM);
    cudaFuncSetAttribute(gru_scan_i8<2>, cudaFuncAttributeMaxDynamicSharedMemorySize, SSM2);
    cudaFuncSetAttribute(gru_scan_i8<1>, cudaFuncAttributeMaxDynamicSharedMemorySize, SSM1);

    const size_t HB = (size_t)2 * B_ * H_;
    const int MT = B_ * T_;
    const float OSC = CSC_;   // (1/16256)*(BND/16256)

    // 1) prep: embed bf16 split, w_ih0 bf16 split, int8 weight splits, bars
    embed_split_kernel<<<MT, 128>>>(tokens, emb, pa0hi, pa0lo);
    split_pad_kernel<<<(2 * G_ * KP0 + 255) / 256, 256>>>(w_ih0, pw0hi, pw0lo, 2 * G_, 300, KP0);
    split_i8_kernel<<<(int)(((size_t)2 * G_ * 1024 + 255) / 256), 256>>>(w_ih1, pw1q1, pw1q0, 2 * G_ * 1024);
    split_i8_kernel<<<(2 * G_ * H_ + 255) / 256, 256>>>(w_hh0, pwh0q1, pwh0q0, 2 * G_ * H_);
    split_i8_kernel<<<(2 * G_ * H_ + 255) / 256, 256>>>(w_hh1, pwh1q1, pwh1q0, 2 * G_ * H_);
    zero_ctr_kernel<<<8, 256>>>(pbar, 2048);

    // 2) layer0 input GEMM (bf16 split): gx0[32768][3072]
    gemm_mma_split<<<dim3(2 * G_ / 128, MT / 128), 256, GSM>>>(
        pa0hi, pa0lo, pw0hi, pw0lo, b_ih0, pgx0, 2 * G_, KP0);

    // 3) layer0 bidirectional scan (int8, persistent, sub-barriers 0..15)
    gru_scan_i8<2><<<dim3(B_ / 64, H_ / 64, 2), 256, SSM2>>>(
        ph, ph + HB, phq1, phq0, phq1 + HB, phq0 + HB,
        pgx0, 2 * G_, G_, pwh0q1, pwh0q0, b_hh0, pyq1, pyq0, pbar);

    // 4) layer1 fwd input GEMM (int8): gx1[32768][1536]
    gemm_i8_split<<<dim3(G_ / 128, MT / 128), 256, GSM>>>(
        pyq1, pyq0, pw1q1, pw1q0, b_ih1, OSC, pgx1, G_, 1024);

    // 5) layer1 forward scan (int8, persistent, sub-barriers 32..39)
    gru_scan_i8<1><<<dim3(B_ / 64, H_ / 32, 1), 256, SSM1>>>(
        ph, ph + HB, phq1, phq0, phq1 + HB, phq0 + HB,
        pgx1, G_, 0, pwh1q1, pwh1q0, b_hh1,
        (int8_t*)nullptr, (int8_t*)nullptr, pbar + 32 * 32);

    // 6) layer1 backward = ONE step at t=T-1 (h0=0), int8 GEMM
    gemm_i8_split<<<dim3(G_ / 128, B_ / 128), 256, GSM>>>(
        pyq1 + (size_t)(T_ - 1) * B_ * 1024, pyq0 + (size_t)(T_ - 1) * B_ * 1024,
        pw1q1 + (size_t)G_ * 1024, pw1q0 + (size_t)G_ * 1024,
        b_ih1 + G_, OSC, pgx1b, G_, 1024);
    bwd1_gates<<<(B_ * H_ + 255) / 256, 256>>>(pgx1b, b_hh1 + G_, plastb);

    // 7) FC head
    fc_kernel<<<B_, 256>>>(ph, plastb, fc_w, fc_b, out);
}

// round 8
// speedup vs baseline: 1.8971x; 1.8971x over previous
#include <cuda_runtime.h>
#include <cuda_bf16.h>
#include <cstdint>

#define B_  512
#define T_  64
#define H_  512
#define G_  1536
#define KP0 320

// ---------------- scratch ----------------------------------------------------
__device__ float g_gx0 [(size_t)B_ * T_ * 2 * G_];
__device__ float g_gx1 [(size_t)B_ * T_ * G_];
__device__ float g_gx1b[(size_t)B_ * G_];
__device__ float g_h   [2 * 2 * B_ * H_];
__device__ float g_lastb[(size_t)B_ * H_];
__device__ unsigned g_bar[2048];
__device__ __align__(16) __nv_bfloat16 g_hhi [2 * 2 * B_ * H_];
__device__ __align__(16) __nv_bfloat16 g_hlo [2 * 2 * B_ * H_];
__device__ __align__(16) __nv_bfloat16 g_a0hi[(size_t)B_ * T_ * KP0];
__device__ __align__(16) __nv_bfloat16 g_a0lo[(size_t)B_ * T_ * KP0];
__device__ __align__(16) __nv_bfloat16 g_w0hi[(size_t)2 * G_ * KP0];
__device__ __align__(16) __nv_bfloat16 g_w0lo[(size_t)2 * G_ * KP0];
__device__ __align__(16) __nv_bfloat16 g_a1hi[(size_t)B_ * T_ * 2 * H_];
__device__ __align__(16) __nv_bfloat16 g_a1lo[(size_t)B_ * T_ * 2 * H_];
__device__ __align__(16) __nv_bfloat16 g_w1hi[(size_t)2 * G_ * 2 * H_];
__device__ __align__(16) __nv_bfloat16 g_w1lo[(size_t)2 * G_ * 2 * H_];
__device__ __align__(16) __nv_bfloat16 g_wh0hi[(size_t)2 * G_ * H_];
__device__ __align__(16) __nv_bfloat16 g_wh0lo[(size_t)2 * G_ * H_];
__device__ __align__(16) __nv_bfloat16 g_wh1hi[(size_t)2 * G_ * H_];
__device__ __align__(16) __nv_bfloat16 g_wh1lo[(size_t)2 * G_ * H_];

// ---------------- helpers ----------------------------------------------------
__device__ __forceinline__ uint32_t smem_u32(const void* p) {
    uint32_t a;
    asm("{ .reg .u64 t; cvta.to.shared.u64 t, %1; cvt.u32.u64 %0, t; }" : "=r"(a) : "l"(p));
    return a;
}
#define CP16(sm, gp)  asm volatile("cp.async.cg.shared.global [%0], [%1], 16;" :: "r"(sm), "l"(gp))
#define CP_COMMIT()   asm volatile("cp.async.commit_group;" ::: "memory")
#define CP_WAIT(n)    asm volatile("cp.async.wait_group %0;" :: "n"(n) : "memory")

__device__ __forceinline__ void ldsm4(uint32_t* r, uint32_t a) {
    asm volatile("ldmatrix.sync.aligned.m8n8.x4.shared.b16 {%0,%1,%2,%3}, [%4];"
        : "=r"(r[0]), "=r"(r[1]), "=r"(r[2]), "=r"(r[3]) : "r"(a));
}
__device__ __forceinline__ void ldsm2(uint32_t* r, uint32_t a) {
    asm volatile("ldmatrix.sync.aligned.m8n8.x2.shared.b16 {%0,%1}, [%2];"
        : "=r"(r[0]), "=r"(r[1]) : "r"(a));
}
__device__ __forceinline__ void mma16816(float* c, const uint32_t* a, const uint32_t* b) {
    asm volatile("mma.sync.aligned.m16n8k16.row.col.f32.bf16.bf16.f32 "
        "{%0,%1,%2,%3},{%4,%5,%6,%7},{%8,%9},{%0,%1,%2,%3};"
        : "+f"(c[0]), "+f"(c[1]), "+f"(c[2]), "+f"(c[3])
        : "r"(a[0]), "r"(a[1]), "r"(a[2]), "r"(a[3]), "r"(b[0]), "r"(b[1]));
}
__device__ __forceinline__ float sigm(float x) { return __fdividef(1.f, 1.f + __expf(-x)); }
__device__ __forceinline__ float tanh_(float x) { return 2.f * sigm(2.f * x) - 1.f; }

__device__ __forceinline__ void grid_bar(unsigned* c, unsigned target) {
    __syncthreads();
    if (threadIdx.x == 0) {
        __threadfence();
        atomicAdd(c, 1u);
        while (atomicAdd(c, 0u) < target) { }
        __threadfence();
    }
    __syncthreads();
}

// ---------------- prep kernels ----------------------------------------------
__global__ void embed_split_kernel(const int* __restrict__ tokens,
                                   const float* __restrict__ emb,
                                   __nv_bfloat16* __restrict__ hi,
                                   __nv_bfloat16* __restrict__ lo)
{
    const int blk = blockIdx.x;
    const int t = blk / B_;
    const int b = blk - t * B_;
    const int tok = tokens[b * T_ + t];
    const float* src = emb + (size_t)tok * 300;
    size_t dst = (size_t)blk * KP0;
    for (int e = threadIdx.x; e < KP0; e += blockDim.x) {
        float v = (e < 300) ? src[e] : 0.f;
        __nv_bfloat16 h = __float2bfloat16(v);
        hi[dst + e] = h;
        lo[dst + e] = __float2bfloat16(v - __bfloat162float(h));
    }
}

__global__ void split_pad_kernel(const float* __restrict__ src,
                                 __nv_bfloat16* __restrict__ hi,
                                 __nv_bfloat16* __restrict__ lo,
                                 int rows, int K, int Kp)
{
    size_t idx = (size_t)blockIdx.x * blockDim.x + threadIdx.x;
    if (idx >= (size_t)rows * Kp) return;
    int r = (int)(idx / Kp);
    int c = (int)(idx - (size_t)r * Kp);
    float v = (c < K) ? src[(size_t)r * K + c] : 0.f;
    __nv_bfloat16 h = __float2bfloat16(v);
    hi[idx] = h;
    lo[idx] = __float2bfloat16(v - __bfloat162float(h));
}

__global__ void zero_ctr_kernel(unsigned* __restrict__ p, int n)
{
    int i = blockIdx.x * blockDim.x + threadIdx.x;
    if (i < n) p[i] = 0u;
}

// ---------------- bf16-split GEMM (input GEMMs; proven) --------------------
#define SSTR 80
#define TILE_B (128 * SSTR)
#define STAGE_B (4 * TILE_B)
__global__ void __launch_bounds__(256, 1)
gemm_mma_split(const __nv_bfloat16* __restrict__ Ahi,
               const __nv_bfloat16* __restrict__ Alo,
               const __nv_bfloat16* __restrict__ Whi,
               const __nv_bfloat16* __restrict__ Wlo,
               const float* __restrict__ bias,
               float* __restrict__ C, int N, int Kp)
{
    extern __shared__ __align__(16) char smem[];
    const int tid = threadIdx.x;
    const int lane = tid & 31;
    const int wid = tid >> 5;
    const int wm = wid & 1, wn = wid >> 1;
    const int m0c = blockIdx.y * 128, n0c = blockIdx.x * 128;
    const int nchunks = Kp >> 5;
    const uint32_t sbase = smem_u32(smem);
    const __nv_bfloat16* bases[4] = { Ahi, Alo, Whi, Wlo };

    auto load_chunk = [&](int c, int s) {
        const uint32_t st = sbase + s * STAGE_B;
        #pragma unroll
        for (int q = 0; q < 8; q++) {
            int g = tid + q * 256;
            int tile = g >> 9, p = g & 511;
            int r = p >> 2, seg = p & 3;
            int rowbase = (tile < 2) ? m0c : n0c;
            CP16(st + tile * TILE_B + r * SSTR + seg * 16,
                 bases[tile] + (size_t)(rowbase + r) * Kp + c * 32 + seg * 8);
        }
        CP_COMMIT();
    };

    float acc[16][4];
    #pragma unroll
    for (int i = 0; i < 16; i++)
        #pragma unroll
        for (int j = 0; j < 4; j++) acc[i][j] = 0.f;

    load_chunk(0, 0);
    for (int c = 0; c < nchunks; c++) {
        const int s = c & 1;
        if (c + 1 < nchunks) { load_chunk(c + 1, s ^ 1); CP_WAIT(1); }
        else                 { CP_WAIT(0); }
        __syncthreads();
        const uint32_t st = sbase + s * STAGE_B;
        #pragma unroll
        for (int kk = 0; kk < 2; kk++) {
            uint32_t ahi[4][4], alo[4][4], bhi[4][2], blo[4][2];
            #pragma unroll
            for (int i = 0; i < 4; i++) {
                int row = wm * 64 + i * 16 + (lane & 15);
                uint32_t off = row * SSTR + kk * 32 + (lane >> 4) * 16;
                ldsm4(ahi[i], st + off);
                ldsm4(alo[i], st + TILE_B + off);
            }
            #pragma unroll
            for (int j = 0; j < 4; j++) {
                int row = wn * 32 + j * 8 + (lane & 7);
                uint32_t off = row * SSTR + kk * 32 + ((lane >> 3) & 1) * 16;
                ldsm2(bhi[j], st + 2 * TILE_B + off);
                ldsm2(blo[j], st + 3 * TILE_B + off);
            }
            #pragma unroll
            for (int i = 0; i < 4; i++)
                #pragma unroll
                for (int j = 0; j < 4; j++) {
                    mma16816(acc[i * 4 + j], ahi[i], bhi[j]);
                    mma16816(acc[i * 4 + j], ahi[i], blo[j]);
                    mma16816(acc[i * 4 + j], alo[i], bhi[j]);
                }
        }
        __syncthreads();
    }
    #pragma unroll
    for (int i = 0; i < 4; i++) {
        int m = m0c + wm * 64 + i * 16 + (lane >> 2);
        #pragma unroll
        for (int j = 0; j < 4; j++) {
            int n = n0c + wn * 32 + j * 8 + (lane & 3) * 2;
            float b0 = bias[n], b1 = bias[n + 1];
            float* a = acc[i * 4 + j];
            float2 v0 = { a[0] + b0, a[1] + b1 };
            float2 v1 = { a[2] + b0, a[3] + b1 };
            *reinterpret_cast<float2*>(C + (size_t)m * N + n) = v0;
            *reinterpret_cast<float2*>(C + (size_t)(m + 8) * N + n) = v1;
        }
    }
}

// ---------------- PERSISTENT W-resident bf16-split GRU scan -----------------
// CTA: MROWS batch x 32 j x 3 gates. W slice (96 rows x 512 K, hi+lo) stays in
// SMEM all 64 steps. A (h hi/lo) streamed per K-chunk(32) via register
// double-buffer. Warps 2m x 4n: n-tile = 8 j x 3 gates (reg-local r/z/n).
#define WSTR 1040
#define W_PL (96 * WSTR)
template<int MROWS>
__global__ void __launch_bounds__(256, 1)
gru_scan_wres(float* __restrict__ h_A, float* __restrict__ h_B,
              __nv_bfloat16* __restrict__ hhi_A, __nv_bfloat16* __restrict__ hlo_A,
              __nv_bfloat16* __restrict__ hhi_B, __nv_bfloat16* __restrict__ hlo_B,
              const float* __restrict__ gx, int gx_ld, int gx_ds,
              const __nv_bfloat16* __restrict__ whh_hi,
              const __nv_bfloat16* __restrict__ whh_lo,
              const float* __restrict__ bhh,
              __nv_bfloat16* __restrict__ y_hi, __nv_bfloat16* __restrict__ y_lo,
              unsigned* __restrict__ bars)
{
    constexpr int A_PL = MROWS * SSTR;          // A plane bytes (stride 80)
    constexpr int SM_A = 2 * W_PL;              // A region base
    constexpr int NPF  = MROWS / 32;            // uint4 prefetch regs/thread
    constexpr int MFRG = MROWS / 32;            // A m-frags per warp
    constexpr int PSH  = (MROWS == 128) ? 9 : 8;

    extern __shared__ __align__(16) char smem[];
    const int tid = threadIdx.x;
    const int lane = tid & 31;
    const int wid = tid >> 5;
    const int wm = wid & 1, wn = wid >> 1;
    const int d  = blockIdx.z;
    const int b0 = blockIdx.x * MROWS;
    const int j0 = blockIdx.y * 32;
    const uint32_t sb = smem_u32(smem);
    unsigned* ctr = bars + (blockIdx.x * gridDim.z + blockIdx.z) * 32;
    const unsigned members = gridDim.y;

    // ---- load W slice once: 96 rows x 512 K, hi+lo, stride 1040 ----
    {
        const __nv_bfloat16* Wh = whh_hi + (size_t)d * G_ * H_;
        const __nv_bfloat16* Wl = whh_lo + (size_t)d * G_ * H_;
        for (int g = tid; g < 96 * 64 * 2; g += 256) {
            int plane = g >= 96 * 64;
            int p = plane ? g - 96 * 64 : g;
            int row = p >> 6, seg = p & 63;
            int grow = (row >> 5) * H_ + j0 + (row & 31);   // gate*512 + j
            CP16(sb + plane * W_PL + row * WSTR + seg * 16,
                 (plane ? Wl : Wh) + (size_t)grow * H_ + seg * 8);
        }
        CP_COMMIT(); CP_WAIT(0);
        __syncthreads();
    }
    const float* bhh_d = bhh + d * G_;

    float* hp = h_A;  float* hn = h_B;
    const __nv_bfloat16 *phh = hhi_A, *phl = hlo_A;
    __nv_bfloat16 *nhh = hhi_B, *nhl = hlo_B;

    for (int s = 0; s < T_; s++) {
        const int t = (d == 0) ? s : (T_ - 1 - s);

        float acc[3][MFRG][4];
        #pragma unroll
        for (int g = 0; g < 3; g++)
            #pragma unroll
            for (int i = 0; i < MFRG; i++)
                #pragma unroll
                for (int r = 0; r < 4; r++) acc[g][i][r] = 0.f;

        if (s > 0) {
            const __nv_bfloat16* Ah = phh + (size_t)d * B_ * H_;
            const __nv_bfloat16* Al = phl + (size_t)d * B_ * H_;
            uint4 pf[NPF];
            auto ldA = [&](int c) {
                #pragma unroll
                for (int q = 0; q < NPF; q++) {
                    int g = tid + q * 256;
                    int plane = g >> PSH;
                    int p = g & ((1 << PSH) - 1);
                    int row = p >> 2, seg = p & 3;
                    pf[q] = *reinterpret_cast<const uint4*>(
                        (plane ? Al : Ah) + (size_t)(b0 + row) * H_ + c * 32 + seg * 8);
                }
            };
            auto stA = [&]() {
                #pragma unroll
                for (int q = 0; q < NPF; q++) {
                    int g = tid + q * 256;
                    int plane = g >> PSH;
                    int p = g & ((1 << PSH) - 1);
                    int row = p >> 2, seg = p & 3;
                    *reinterpret_cast<uint4*>(
                        smem + SM_A + plane * A_PL + row * SSTR + seg * 16) = pf[q];
                }
            };

            ldA(0);
            for (int c = 0; c < 16; c++) {
                stA();
                __syncthreads();
                if (c + 1 < 16) ldA(c + 1);
                #pragma unroll
                for (int kk = 0; kk < 2; kk++) {
                    uint32_t ah[MFRG][4], al[MFRG][4];
                    #pragma unroll
                    for (int i = 0; i < MFRG; i++) {
                        int row = wm * (MROWS / 2) + i * 16 + (lane & 15);
                        uint32_t off = SM_A + row * SSTR + kk * 32 + (lane >> 4) * 16;
                        ldsm4(ah[i], sb + off);
                        ldsm4(al[i], sb + off + A_PL);
                    }
                    uint32_t bh[3][2], bl[3][2];
                    #pragma unroll
                    for (int g = 0; g < 3; g++) {
                        int row = g * 32 + wn * 8 + (lane & 7);
                        uint32_t off = row * WSTR + c * 64 + kk * 32 + ((lane >> 3) & 1) * 16;
                        ldsm2(bh[g], sb + off);
                        ldsm2(bl[g], sb + off + W_PL);
                    }
                    #pragma unroll
                    for (int g = 0; g < 3; g++)
                        #pragma unroll
                        for (int i = 0; i < MFRG; i++) {
                            mma16816(acc[g][i], ah[i], bh[g]);
                            mma16816(acc[g][i], ah[i], bl[g]);
                            mma16816(acc[g][i], al[i], bh[g]);
                        }
                }
                __syncthreads();
            }
        }

        // -------- gate epilogue --------
        #pragma unroll
        for (int i = 0; i < MFRG; i++)
            #pragma unroll
            for (int half = 0; half < 2; half++) {
                int b = b0 + wm * (MROWS / 2) + i * 16 + (lane >> 2) + half * 8;
                size_t row = (size_t)t * B_ + b;
                const float* gxr = gx + row * gx_ld + (size_t)d * gx_ds;
                const float* hpr = hp + ((size_t)d * B_ + b) * H_;
                int jc = j0 + wn * 8 + (lane & 3) * 2;
                #pragma unroll
                for (int e = 0; e < 2; e++) {
                    int j = jc + e;
                    float ghr = acc[0][i][half * 2 + e] + bhh_d[j];
                    float ghz = acc[1][i][half * 2 + e] + bhh_d[H_ + j];
                    float ghn = acc[2][i][half * 2 + e] + bhh_d[2 * H_ + j];
                    float rg = sigm(gxr[j] + ghr);
                    float zg = sigm(gxr[H_ + j] + ghz);
                    float ng = tanh_(gxr[2 * H_ + j] + rg * ghn);
                    float hprev = (s > 0) ? hpr[j] : 0.f;
                    float hv = (1.f - zg) * ng + zg * hprev;
                    size_t ho = ((size_t)d * B_ + b) * H_ + j;
                    hn[ho] = hv;
                    __nv_bfloat16 hib = __float2bfloat16(hv);
                    __nv_bfloat16 lob = __float2bfloat16(hv - __bfloat162float(hib));
                    nhh[ho] = hib;
                    nhl[ho] = lob;
                    if (y_hi) {
                        size_t yo = row * (size_t)(2 * H_) + (size_t)d * H_ + j;
                        y_hi[yo] = hib;
                        y_lo[yo] = lob;
                    }
                }
            }

        grid_bar(ctr, (unsigned)(s + 1) * members);

        float* tf = hp; hp = hn; hn = tf;
        const __nv_bfloat16* th = phh; phh = nhh; nhh = (__nv_bfloat16*)th;
        const __nv_bfloat16* tl = phl; phl = nhl; nhl = (__nv_bfloat16*)tl;
    }
}

// ---------------- tail kernels ----------------------------------------------
__global__ void bwd1_gates(const float* __restrict__ gxb,
                           const float* __restrict__ bhh,
                           float* __restrict__ out)
{
    int idx = blockIdx.x * blockDim.x + threadIdx.x;
    if (idx >= B_ * H_) return;
    int b = idx >> 9, j = idx & 511;
    const float* r0 = gxb + (size_t)b * G_;
    float rg = sigm(r0[j] + bhh[j]);
    float zg = sigm(r0[H_ + j] + bhh[H_ + j]);
    float ng = tanh_(r0[2 * H_ + j] + rg * bhh[2 * H_ + j]);
    out[idx] = (1.f - zg) * ng;
}

__global__ void fc_kernel(const float* __restrict__ hf, const float* __restrict__ hb,
                          const float* __restrict__ fcw, const float* __restrict__ fcb,
                          float* __restrict__ out)
{
    int b = blockIdx.x, tid = threadIdx.x;
    float s0 = 0.f, s1 = 0.f;
    for (int j = tid; j < 1024; j += 256) {
        float v = (j < 512) ? hf[(size_t)b * 512 + j] : hb[(size_t)b * 512 + (j - 512)];
        s0 += v * fcw[j];
        s1 += v * fcw[1024 + j];
    }
    __shared__ float red0[256], red1[256];
    red0[tid] = s0; red1[tid] = s1;
    __syncthreads();
    for (int off = 128; off > 0; off >>= 1) {
        if (tid < off) { red0[tid] += red0[tid + off]; red1[tid] += red1[tid + off]; }
        __syncthreads();
    }
    if (tid == 0) {
        out[b * 2 + 0] = red0[0] + fcb[0];
        out[b * 2 + 1] = red1[0] + fcb[1];
    }
}

// ---------------- launch -----------------------------------------------------
extern "C" void kernel_launch(void* const* d_in, const int* in_sizes, int n_in,
                              void* d_out, int out_size)
{
    (void)in_sizes; (void)n_in; (void)out_size;
    const int*   tokens = (const int*)  d_in[0];
    const float* emb    = (const float*)d_in[1];
    const float* w_ih0  = (const float*)d_in[2];
    const float* w_hh0  = (const float*)d_in[3];
    const float* b_ih0  = (const float*)d_in[4];
    const float* b_hh0  = (const float*)d_in[5];
    const float* w_ih1  = (const float*)d_in[6];
    const float* w_hh1  = (const float*)d_in[7];
    const float* b_ih1  = (const float*)d_in[8];
    const float* b_hh1  = (const float*)d_in[9];
    const float* fc_w   = (const float*)d_in[10];
    const float* fc_b   = (const float*)d_in[11];
    float* out = (float*)d_out;

    float *pgx0, *pgx1, *pgx1b, *ph, *plastb;
    unsigned* pbar;
    cudaGetSymbolAddress((void**)&pgx0,   g_gx0);
    cudaGetSymbolAddress((void**)&pgx1,   g_gx1);
    cudaGetSymbolAddress((void**)&pgx1b,  g_gx1b);
    cudaGetSymbolAddress((void**)&ph,     g_h);
    cudaGetSymbolAddress((void**)&plastb, g_lastb);
    cudaGetSymbolAddress((void**)&pbar,   g_bar);
    __nv_bfloat16 *phhi, *phlo, *pa0hi, *pa0lo, *pw0hi, *pw0lo;
    __nv_bfloat16 *pa1hi, *pa1lo, *pw1hi, *pw1lo, *pwh0hi, *pwh0lo, *pwh1hi, *pwh1lo;
    cudaGetSymbolAddress((void**)&phhi,  g_hhi);
    cudaGetSymbolAddress((void**)&phlo,  g_hlo);
    cudaGetSymbolAddress((void**)&pa0hi, g_a0hi);
    cudaGetSymbolAddress((void**)&pa0lo, g_a0lo);
    cudaGetSymbolAddress((void**)&pw0hi, g_w0hi);
    cudaGetSymbolAddress((void**)&pw0lo, g_w0lo);
    cudaGetSymbolAddress((void**)&pa1hi, g_a1hi);
    cudaGetSymbolAddress((void**)&pa1lo, g_a1lo);
    cudaGetSymbolAddress((void**)&pw1hi, g_w1hi);
    cudaGetSymbolAddress((void**)&pw1lo, g_w1lo);
    cudaGetSymbolAddress((void**)&pwh0hi, g_wh0hi);
    cudaGetSymbolAddress((void**)&pwh0lo, g_wh0lo);
    cudaGetSymbolAddress((void**)&pwh1hi, g_wh1hi);
    cudaGetSymbolAddress((void**)&pwh1lo, g_wh1lo);

    const int GSM  = 2 * STAGE_B;                       // 81920
    const int SCM0 = 2 * W_PL + 2 * 128 * SSTR;         // 220160 (MROWS=128)
    const int SCM1 = 2 * W_PL + 2 * 64 * SSTR;          // 209920 (MROWS=64)
    cudaFuncSetAttribute(gemm_mma_split, cudaFuncAttributeMaxDynamicSharedMemorySize, GSM);
    cudaFuncSetAttribute(gru_scan_wres<128>, cudaFuncAttributeMaxDynamicSharedMemorySize, SCM0);
    cudaFuncSetAttribute(gru_scan_wres<64>,  cudaFuncAttributeMaxDynamicSharedMemorySize, SCM1);

    const size_t HB = (size_t)2 * B_ * H_;
    const int MT = B_ * T_;

    // 1) prep
    embed_split_kernel<<<MT, 128>>>(tokens, emb, pa0hi, pa0lo);
    split_pad_kernel<<<(2 * G_ * KP0 + 255) / 256, 256>>>(w_ih0, pw0hi, pw0lo, 2 * G_, 300, KP0);
    split_pad_kernel<<<(int)(((size_t)2 * G_ * 1024 + 255) / 256), 256>>>(w_ih1, pw1hi, pw1lo, 2 * G_, 1024, 1024);
    split_pad_kernel<<<(2 * G_ * H_ + 255) / 256, 256>>>(w_hh0, pwh0hi, pwh0lo, 2 * G_, H_, H_);
    split_pad_kernel<<<(2 * G_ * H_ + 255) / 256, 256>>>(w_hh1, pwh1hi, pwh1lo, 2 * G_, H_, H_);
    zero_ctr_kernel<<<8, 256>>>(pbar, 2048);

    // 2) layer0 input GEMM: gx0[32768][3072]
    gemm_mma_split<<<dim3(2 * G_ / 128, MT / 128), 256, GSM>>>(
        pa0hi, pa0lo, pw0hi, pw0lo, b_ih0, pgx0, 2 * G_, KP0);

    // 3) layer0 bidirectional scan: persistent, W-resident (128 CTAs)
    gru_scan_wres<128><<<dim3(4, 16, 2), 256, SCM0>>>(
        ph, ph + HB, phhi, phlo, phhi + HB, phlo + HB,
        pgx0, 2 * G_, G_, pwh0hi, pwh0lo, b_hh0, pa1hi, pa1lo, pbar);

    // 4) layer1 fwd input GEMM: gx1[32768][1536]
    gemm_mma_split<<<dim3(G_ / 128, MT / 128), 256, GSM>>>(
        pa1hi, pa1lo, pw1hi, pw1lo, b_ih1, pgx1, G_, 1024);

    // 5) layer1 forward scan: persistent, W-resident (128 CTAs)
    gru_scan_wres<64><<<dim3(8, 16, 1), 256, SCM1>>>(
        ph, ph + HB, phhi, phlo, phhi + HB, phlo + HB,
        pgx1, G_, 0, pwh1hi, pwh1lo, b_hh1,
        (__nv_bfloat16*)nullptr, (__nv_bfloat16*)nullptr, pbar + 1024);

    // 6) layer1 backward = ONE step at t=T-1 (h0=0)
    gemm_mma_split<<<dim3(G_ / 128, B_ / 128), 256, GSM>>>(
        pa1hi + (size_t)(T_ - 1) * B_ * 1024, pa1lo + (size_t)(T_ - 1) * B_ * 1024,
        pw1hi + (size_t)G_ * 1024, pw1lo + (size_t)G_ * 1024,
        b_ih1 + G_, pgx1b, G_, 1024);
    bwd1_gates<<<(B_ * H_ + 255) / 256, 256>>>(pgx1b, b_hh1 + G_, plastb);

    // 7) FC head
    fc_kernel<<<B_, 256>>>(ph, plastb, fc_w, fc_b, out);
}